// round 10
// baseline (speedup 1.0000x reference)
#include <cuda_runtime.h>
#include <cuda_bf16.h>
#include <math.h>
#include <stdint.h>

namespace {
constexpr int kS = 2048;
constexpr int kB = 32;
constexpr int kD = 256;
constexpr int kH = 4;
constexpr int kN = kS * kB;
constexpr float kEps = 1e-5f;
// smem: A bf16 2x16K | B 3x16K | affine 2K
constexpr int kOffB = 32768;
constexpr int kOffAff = 81920;
constexpr int kSmemTotal = 83968;
}  // namespace

__device__ float g_bufq[2][(size_t)kN * kD];
__device__ float g_bufk[2][(size_t)kN * kD];
__device__ float g_bufv[2][(size_t)kN * kD];
__device__ float g_t2[(size_t)kN * kD];
__device__ float g_s1a[kD], g_s2a[kD], g_s1b[kD], g_s2b[kD];
__device__ float g_se[kB * kD], g_wv[kB * kD];
__device__ float g_concat[kB * kH * kD];
// Weight image: [matrix][chunk c<8][n<256][128B row: hi gran 0-3 | lo gran 4-7,
// granule u at byte ((u ^ (n&7))<<4)]. 256KB per matrix.
__device__ unsigned char g_wimg[20 * 262144];

__device__ __forceinline__ uint32_t smem_u32(const void* p) {
    uint32_t a;
    asm("{ .reg .u64 t; cvta.to.shared.u64 t, %1; cvt.u32.u64 %0, t; }"
        : "=r"(a) : "l"(p));
    return a;
}
__device__ __forceinline__ void cp16(uint32_t dst, const void* src) {
    asm volatile("cp.async.cg.shared.global [%0], [%1], 16;" :: "r"(dst), "l"(src));
}
#define CP_COMMIT() asm volatile("cp.async.commit_group;" ::: "memory")
#define CP_WAIT0()  asm volatile("cp.async.wait_group 0;" ::: "memory")
#define CP_WAIT1()  asm volatile("cp.async.wait_group 1;" ::: "memory")

__device__ __forceinline__ void ldmx4(uint32_t* r, uint32_t addr) {
    asm volatile("ldmatrix.sync.aligned.m8n8.x4.shared.b16 {%0,%1,%2,%3}, [%4];"
                 : "=r"(r[0]), "=r"(r[1]), "=r"(r[2]), "=r"(r[3]) : "r"(addr));
}
__device__ __forceinline__ void mma16816(float* d, const uint32_t* a,
                                         uint32_t b0, uint32_t b1) {
    asm volatile(
        "mma.sync.aligned.m16n8k16.row.col.f32.bf16.bf16.f32 "
        "{%0,%1,%2,%3}, {%4,%5,%6,%7}, {%8,%9}, {%0,%1,%2,%3};"
        : "+f"(d[0]), "+f"(d[1]), "+f"(d[2]), "+f"(d[3])
        : "r"(a[0]), "r"(a[1]), "r"(a[2]), "r"(a[3]), "r"(b0), "r"(b1));
}

__global__ void preconvert_w(const float* __restrict__ wq, const float* __restrict__ wk,
                             const float* __restrict__ wv, const float* __restrict__ wl1,
                             const float* __restrict__ wl2) {
    const int g = blockIdx.x;
    const int slot = g >> 2, head = g & 3;
    const float* src;
    switch (slot) {
        case 0: src = wq; break;
        case 1: src = wk; break;
        case 2: src = wv; break;
        case 3: src = wl1; break;
        default: src = wl2; break;
    }
    src += (size_t)head * kD * kD;
    unsigned char* img = g_wimg + (size_t)g * 262144;
    const int idx = blockIdx.y * 256 + threadIdx.x;
    const int n = idx >> 4;
    const int k0 = (idx & 15) * 16;
    const int nx = n & 7;
#pragma unroll
    for (int j = 0; j < 16; ++j) {
        const int k = k0 + j;
        const float x = src[n * kD + k];
        const __nv_bfloat16 h = __float2bfloat16(x);
        const __nv_bfloat16 l = __float2bfloat16(x - __bfloat162float(h));
        const int c = k >> 5, kl = k & 31;
        const int u = kl >> 3, e2 = (kl & 7) * 2;
        unsigned char* row = img + ((size_t)(c * 256 + n) << 7);
        *(__nv_bfloat16*)(row + ((u ^ nx) << 4) + e2) = h;
        *(__nv_bfloat16*)(row + (((u + 4) ^ nx) << 4) + e2) = l;
    }
}

// ---------------------------------------------------------------------------
// GEMM + fused prologue/epilogues. CTA tile 128x128, K in 8 chunks of 32.
// Grid (2, 512), 256 threads (8 warps 2m x 4n), 2 CTAs/SM, triple-buffered B.
// MODE: 0 plain; 1 relu((A-A2)*sc+sh); 2 relu(A*sc+sh)  (sc/sh computed
//       in-kernel from raw stats s1/s2 + gamma/beta)
// EPI : 0 store; 1 store+col-stats(C-aux); 2 store+col-stats(C);
//       3 no store: smem-reduced softmax accum st1+=exp, st2+=exp*aux
// Z   : 1 -> CTA(0,0) zeroes all stats/softmax accumulators at start
// ---------------------------------------------------------------------------
template <int MODE, int EPI, int Z>
__global__ void __launch_bounds__(256, 2)
gemm_u(const float* __restrict__ A, const float* __restrict__ A2,
       const float* __restrict__ s1, const float* __restrict__ s2,
       const float* __restrict__ gamma, const float* __restrict__ beta,
       const unsigned char* __restrict__ Wimg, const float* __restrict__ bias,
       float* __restrict__ C, const float* __restrict__ aux,
       float* __restrict__ st1, float* __restrict__ st2) {
    extern __shared__ __align__(1024) char smem[];
    const uint32_t sb = smem_u32(smem);
    const int tid = threadIdx.x;
    const int lane = tid & 31, warp = tid >> 5;
    const int wm = warp >> 2, wn = warp & 3;
    const int n0 = blockIdx.x * 128;
    const int m0 = blockIdx.y * 128;

    if (Z) {
        if (blockIdx.x == 0 && blockIdx.y == 0) {
            for (int t = tid; t < kB * kD; t += 256) { g_se[t] = 0.f; g_wv[t] = 0.f; }
            g_s1a[tid] = 0.f; g_s2a[tid] = 0.f; g_s1b[tid] = 0.f; g_s2b[tid] = 0.f;
        }
    }

    float* scS = (float*)(smem + kOffAff);
    float* shS = scS + 256;
    if (MODE != 0) {
        // BN affine from raw sums (all 256 channels, one per thread)
        const double mean = (double)s1[tid] / (double)kN;
        const double var = (double)s2[tid] / (double)kN - mean * mean;
        const float rs = (float)rsqrt(var + (double)kEps);
        const float scv = rs * gamma[tid];
        scS[tid] = scv;
        shS[tid] = beta[tid] - (float)mean * scv;
        __syncthreads();
    }

    float acc[4][4][4];
#pragma unroll
    for (int i = 0; i < 4; ++i)
#pragma unroll
        for (int j = 0; j < 4; ++j)
#pragma unroll
            for (int e = 0; e < 4; ++e) acc[i][j][e] = 0.f;

    const int ar = tid >> 1, ahalf = tid & 1, arx = ar & 7;
    float va[16];

    auto ldgA = [&](int c) {
        const size_t base = (size_t)(m0 + ar) * kD + c * 32 + ahalf * 16;
        float4 t[4];
#pragma unroll
        for (int j = 0; j < 4; ++j) t[j] = *(const float4*)(A + base + j * 4);
        if (MODE == 1) {
#pragma unroll
            for (int j = 0; j < 4; ++j) {
                const float4 q = *(const float4*)(A2 + base + j * 4);
                t[j].x -= q.x; t[j].y -= q.y; t[j].z -= q.z; t[j].w -= q.w;
            }
        }
        if (MODE != 0) {
            const int kb = c * 32 + ahalf * 16;
#pragma unroll
            for (int j = 0; j < 4; ++j) {
                const float4 s4 = *(const float4*)(scS + kb + j * 4);
                const float4 h4 = *(const float4*)(shS + kb + j * 4);
                t[j].x = fmaxf(t[j].x * s4.x + h4.x, 0.f);
                t[j].y = fmaxf(t[j].y * s4.y + h4.y, 0.f);
                t[j].z = fmaxf(t[j].z * s4.z + h4.z, 0.f);
                t[j].w = fmaxf(t[j].w * s4.w + h4.w, 0.f);
            }
        }
#pragma unroll
        for (int j = 0; j < 4; ++j) {
            va[j * 4 + 0] = t[j].x; va[j * 4 + 1] = t[j].y;
            va[j * 4 + 2] = t[j].z; va[j * 4 + 3] = t[j].w;
        }
    };

    auto stsA = [&](int s) {
        char* ap = smem + s * 16384 + ar * 128;
#pragma unroll
        for (int q = 0; q < 2; ++q) {
            union { __nv_bfloat16 h[8]; uint4 u; } H, L;
#pragma unroll
            for (int e = 0; e < 8; ++e) {
                const float v = va[q * 8 + e];
                H.h[e] = __float2bfloat16(v);
                L.h[e] = __float2bfloat16(v - __bfloat162float(H.h[e]));
            }
            const int u = ahalf * 2 + q;
            *(uint4*)(ap + ((u ^ arx) << 4)) = H.u;
            *(uint4*)(ap + (((u + 4) ^ arx) << 4)) = L.u;
        }
    };

    auto cpB = [&](int c, int s) {
        const int r = tid >> 1, hf = tid & 1;
        const unsigned char* src = Wimg + (((size_t)(c * 256 + n0 + r)) << 7) + hf * 64;
        const uint32_t dst = sb + kOffB + s * 16384 + r * 128 + hf * 64;
#pragma unroll
        for (int g = 0; g < 4; ++g) cp16(dst + g * 16, src + g * 16);
    };

    const int lidx = lane >> 3, rowoff = lane & 7;
    const int mrow = (lidx & 1) * 8 + rowoff;
    const int halfbit = lidx >> 1;
    int rowA[4], rowB[2];
#pragma unroll
    for (int i = 0; i < 4; ++i) rowA[i] = (wm * 64 + i * 16 + mrow) * 128;
#pragma unroll
    for (int j = 0; j < 2; ++j) rowB[j] = (wn * 32 + j * 16 + mrow) * 128;

    auto compute = [&](int c) {
        const uint32_t aB = sb + (c & 1) * 16384;
        const uint32_t bB = sb + kOffB + (c % 3) * 16384;
#pragma unroll
        for (int ks = 0; ks < 2; ++ks) {
            const int uh = ks * 2 + halfbit;
            const int posH = ((uh ^ rowoff) << 4);
            const int posL = (((uh + 4) ^ rowoff) << 4);
            uint32_t ah[4][4], bh[2][4], bl[2][4];
#pragma unroll
            for (int i = 0; i < 4; ++i) ldmx4(ah[i], aB + rowA[i] + posH);
#pragma unroll
            for (int j = 0; j < 2; ++j) ldmx4(bh[j], bB + rowB[j] + posH);
#pragma unroll
            for (int j = 0; j < 2; ++j) ldmx4(bl[j], bB + rowB[j] + posL);
#pragma unroll
            for (int i = 0; i < 4; ++i)
#pragma unroll
                for (int j = 0; j < 4; ++j)
                    mma16816(acc[i][j], ah[i], bh[j >> 1][j & 1], bh[j >> 1][2 + (j & 1)]);
#pragma unroll
            for (int i = 0; i < 4; ++i)
#pragma unroll
                for (int j = 0; j < 4; ++j)
                    mma16816(acc[i][j], ah[i], bl[j >> 1][j & 1], bl[j >> 1][2 + (j & 1)]);
#pragma unroll
            for (int i = 0; i < 4; ++i) ldmx4(ah[i], aB + rowA[i] + posL);
#pragma unroll
            for (int i = 0; i < 4; ++i)
#pragma unroll
                for (int j = 0; j < 4; ++j)
                    mma16816(acc[i][j], ah[i], bh[j >> 1][j & 1], bh[j >> 1][2 + (j & 1)]);
        }
    };

    // ---- mainloop: A double-buffered regs->smem, B triple-buffered cp.async
    ldgA(0);
    cpB(0, 0); CP_COMMIT();
    cpB(1, 1); CP_COMMIT();
    stsA(0);
#pragma unroll 1
    for (int c = 0; c < 8; ++c) {
        if (c == 7) { CP_WAIT0(); } else { CP_WAIT1(); }
        __syncthreads();
        if (c < 6) { cpB(c + 2, (c + 2) % 3); CP_COMMIT(); }
        if (c < 7) ldgA(c + 1);
        compute(c);
        if (c < 7) stsA((c + 1) & 1);
    }

    // ---- epilogues ----
    const int er = lane >> 2, ec = (lane & 3) * 2;
    if (EPI == 3) {
        __syncthreads();
        float* se_s = (float*)smem;          // [32][128]
        float* wv_s = se_s + 4096;           // [32][128]
        for (int t = tid; t < 8192; t += 256) se_s[t] = 0.f;
        __syncthreads();
#pragma unroll
        for (int i = 0; i < 4; ++i) {
            const int mr = m0 + wm * 64 + i * 16 + er;
#pragma unroll
            for (int j = 0; j < 4; ++j) {
                const int ncl = wn * 32 + j * 8 + ec;
                const float2 v0 = *(const float2*)(aux + (size_t)mr * kD + n0 + ncl);
                const float2 v1 = *(const float2*)(aux + (size_t)(mr + 8) * kD + n0 + ncl);
                const float e0 = __expf(acc[i][j][0]);
                const float e1 = __expf(acc[i][j][1]);
                const float e2 = __expf(acc[i][j][2]);
                const float e3 = __expf(acc[i][j][3]);
                const int b0 = (mr & 31) * 128 + ncl;
                const int b1 = ((mr + 8) & 31) * 128 + ncl;
                atomicAdd(&se_s[b0 + 0], e0);
                atomicAdd(&se_s[b0 + 1], e1);
                atomicAdd(&se_s[b1 + 0], e2);
                atomicAdd(&se_s[b1 + 1], e3);
                atomicAdd(&wv_s[b0 + 0], e0 * v0.x);
                atomicAdd(&wv_s[b0 + 1], e1 * v0.y);
                atomicAdd(&wv_s[b1 + 0], e2 * v1.x);
                atomicAdd(&wv_s[b1 + 1], e3 * v1.y);
            }
        }
        __syncthreads();
        for (int t = tid; t < 4096; t += 256) {
            const int b = t >> 7, ncl = t & 127;
            atomicAdd(&st1[b * kD + n0 + ncl], se_s[t]);
            atomicAdd(&st2[b * kD + n0 + ncl], wv_s[t]);
        }
    } else {
        float s1l[8], s2l[8];
#pragma unroll
        for (int t = 0; t < 8; ++t) { s1l[t] = 0.f; s2l[t] = 0.f; }
#pragma unroll
        for (int i = 0; i < 4; ++i) {
            const int mr = m0 + wm * 64 + i * 16 + er;
#pragma unroll
            for (int j = 0; j < 4; ++j) {
                const int nc = n0 + wn * 32 + j * 8 + ec;
                const float2 b2 = *(const float2*)(bias + nc);
                float2 o0, o1;
                o0.x = acc[i][j][0] + b2.x; o0.y = acc[i][j][1] + b2.y;
                o1.x = acc[i][j][2] + b2.x; o1.y = acc[i][j][3] + b2.y;
                *(float2*)(C + (size_t)mr * kD + nc) = o0;
                *(float2*)(C + (size_t)(mr + 8) * kD + nc) = o1;
                if (EPI != 0) {
                    float x0 = o0.x, x1 = o0.y, x2 = o1.x, x3 = o1.y;
                    if (EPI == 1) {
                        const float2 q0 = *(const float2*)(aux + (size_t)mr * kD + nc);
                        const float2 q1 = *(const float2*)(aux + (size_t)(mr + 8) * kD + nc);
                        x0 -= q0.x; x1 -= q0.y; x2 -= q1.x; x3 -= q1.y;
                    }
                    s1l[j * 2 + 0] += x0 + x2;
                    s1l[j * 2 + 1] += x1 + x3;
                    s2l[j * 2 + 0] += x0 * x0 + x2 * x2;
                    s2l[j * 2 + 1] += x1 * x1 + x3 * x3;
                }
            }
        }
        if (EPI != 0) {
#pragma unroll
            for (int off = 4; off < 32; off <<= 1) {
#pragma unroll
                for (int t = 0; t < 8; ++t) {
                    s1l[t] += __shfl_xor_sync(0xffffffffu, s1l[t], off);
                    s2l[t] += __shfl_xor_sync(0xffffffffu, s2l[t], off);
                }
            }
            if (lane < 4) {
#pragma unroll
                for (int t = 0; t < 8; ++t) {
                    const int nc = n0 + wn * 32 + (t >> 1) * 8 + lane * 2 + (t & 1);
                    atomicAdd(&st1[nc], s1l[t]);
                    atomicAdd(&st2[nc], s2l[t]);
                }
            }
        }
    }
}

__global__ void softmax_final_kernel(const float* __restrict__ se,
                                     const float* __restrict__ wv,
                                     float* __restrict__ concat, int head) {
    const int b = blockIdx.x;
    const int d = threadIdx.x;
    concat[b * (kH * kD) + head * kD + d] = wv[b * kD + d] / se[b * kD + d];
}

__global__ void __launch_bounds__(256)
mlp_kernel(const float* __restrict__ concat,
           const float* __restrict__ mw0, const float* __restrict__ mb0,
           const float* __restrict__ mw1, const float* __restrict__ mb1,
           const float* __restrict__ mw2, const float* __restrict__ mb2,
           float* __restrict__ out) {
    __shared__ float xs[kH * kD];
    __shared__ float h0[kD];
    __shared__ float h1[kD];
    const int b = blockIdx.x;
    const int j = threadIdx.x;
    for (int t = j; t < kH * kD; t += kD) xs[t] = concat[b * kH * kD + t];
    __syncthreads();
    float acc = mb0[j];
    for (int t = 0; t < kH * kD; t++) acc += xs[t] * mw0[(size_t)j * (kH * kD) + t];
    h0[j] = fmaxf(acc, 0.f);
    __syncthreads();
    acc = mb1[j];
    for (int t = 0; t < kD; t++) acc += h0[t] * mw1[(size_t)j * kD + t];
    h1[j] = fmaxf(acc, 0.f);
    __syncthreads();
    acc = mb2[j];
    for (int t = 0; t < kD; t++) acc += h1[t] * mw2[(size_t)j * kD + t];
    out[b * kD + j] = acc;
}

extern "C" void kernel_launch(void* const* d_in, const int* in_sizes, int n_in,
                              void* d_out, int out_size) {
    (void)in_sizes; (void)n_in; (void)out_size;
    const float* in_q  = (const float*)d_in[0];
    const float* in_k  = (const float*)d_in[1];
    const float* in_v  = (const float*)d_in[2];
    const float* wq    = (const float*)d_in[3];
    const float* bqv   = (const float*)d_in[4];
    const float* wk    = (const float*)d_in[5];
    const float* bkv   = (const float*)d_in[6];
    const float* wvw   = (const float*)d_in[7];
    const float* bvv   = (const float*)d_in[8];
    const float* g1    = (const float*)d_in[9];
    const float* be1   = (const float*)d_in[10];
    const float* wl1   = (const float*)d_in[11];
    const float* bl1   = (const float*)d_in[12];
    const float* g2    = (const float*)d_in[13];
    const float* be2   = (const float*)d_in[14];
    const float* wl2   = (const float*)d_in[15];
    const float* bl2   = (const float*)d_in[16];
    const float* mw0   = (const float*)d_in[17];
    const float* mb0   = (const float*)d_in[18];
    const float* mw1   = (const float*)d_in[19];
    const float* mb1   = (const float*)d_in[20];
    const float* mw2   = (const float*)d_in[21];
    const float* mb2   = (const float*)d_in[22];

    float *bq, *bk, *bv, *t2, *se, *wv, *concat;
    float *s1a, *s2a, *s1b, *s2b;
    unsigned char* wimg;
    cudaGetSymbolAddress((void**)&bq, g_bufq);
    cudaGetSymbolAddress((void**)&bk, g_bufk);
    cudaGetSymbolAddress((void**)&bv, g_bufv);
    cudaGetSymbolAddress((void**)&t2, g_t2);
    cudaGetSymbolAddress((void**)&s1a, g_s1a);
    cudaGetSymbolAddress((void**)&s2a, g_s2a);
    cudaGetSymbolAddress((void**)&s1b, g_s1b);
    cudaGetSymbolAddress((void**)&s2b, g_s2b);
    cudaGetSymbolAddress((void**)&se, g_se);
    cudaGetSymbolAddress((void**)&wv, g_wv);
    cudaGetSymbolAddress((void**)&concat, g_concat);
    cudaGetSymbolAddress((void**)&wimg, g_wimg);

    cudaFuncSetAttribute(gemm_u<0,0,1>, cudaFuncAttributeMaxDynamicSharedMemorySize, kSmemTotal);
    cudaFuncSetAttribute(gemm_u<0,0,0>, cudaFuncAttributeMaxDynamicSharedMemorySize, kSmemTotal);
    cudaFuncSetAttribute(gemm_u<0,1,0>, cudaFuncAttributeMaxDynamicSharedMemorySize, kSmemTotal);
    cudaFuncSetAttribute(gemm_u<1,2,0>, cudaFuncAttributeMaxDynamicSharedMemorySize, kSmemTotal);
    cudaFuncSetAttribute(gemm_u<2,3,0>, cudaFuncAttributeMaxDynamicSharedMemorySize, kSmemTotal);

    preconvert_w<<<dim3(20, 16), 256>>>(wq, wk, wvw, wl1, wl2);

    const size_t bufElems = (size_t)kN * kD;
    const dim3 gg(kD / 128, kN / 128);  // (2, 512)

    auto W = [&](int slot, int head) {
        return wimg + (size_t)(slot * 4 + head) * 262144;
    };

    const float *qin = in_q, *kin = in_k, *vin = in_v;
    for (int i = 0; i < kH; i++) {
        float* qout = bq + (size_t)(i & 1) * bufElems;
        float* kout = bk + (size_t)(i & 1) * bufElems;
        float* vout = bv + (size_t)(i & 1) * bufElems;

        // q projection; CTA(0,0) zeroes this head's accumulators
        gemm_u<0,0,1><<<gg, 256, kSmemTotal>>>(qin, nullptr, nullptr, nullptr,
            nullptr, nullptr, W(0,i), bqv + i*kD, qout, nullptr, nullptr, nullptr);
        gemm_u<0,0,0><<<gg, 256, kSmemTotal>>>(vin, nullptr, nullptr, nullptr,
            nullptr, nullptr, W(2,i), bvv + i*kD, vout, nullptr, nullptr, nullptr);
        // k projection + fused BN1 stats of (k' - q')
        gemm_u<0,1,0><<<gg, 256, kSmemTotal>>>(kin, nullptr, nullptr, nullptr,
            nullptr, nullptr, W(1,i), bkv + i*kD, kout, qout, s1a, s2a);

        // linear1 on relu(bn(k'-q')) (affine from s1a/s2a in-kernel) + BN2 stats
        gemm_u<1,2,0><<<gg, 256, kSmemTotal>>>(kout, qout, s1a, s2a,
            g1 + i*kD, be1 + i*kD, W(3,i), bl1 + i*kD, t2, nullptr, s1b, s2b);

        // linear2 (affine from s1b/s2b) + fused softmax accum against v'
        gemm_u<2,3,0><<<gg, 256, kSmemTotal>>>(t2, nullptr, s1b, s2b,
            g2 + i*kD, be2 + i*kD, W(4,i), bl2 + i*kD, nullptr, vout, se, wv);

        softmax_final_kernel<<<kB, 256>>>(se, wv, concat, i);

        qin = qout; kin = kout; vin = vout;
    }

    mlp_kernel<<<kB, 256>>>(concat, mw0, mb0, mw1, mb1, mw2, mb2, (float*)d_out);
}